// round 2
// baseline (speedup 1.0000x reference)
#include <cuda_runtime.h>
#include <cuda_bf16.h>
#include <stdint.h>

#define ATOMS   4096
#define DMODEL  16384
#define BATCH   32
#define ITERS   10
#define TEMP    0.001f

#define KCHUNKS 8
#define KCHUNK  (DMODEL / KCHUNKS)   // 2048
#define ATILE   64                   // atoms per CTA
#define NTILES  (ATOMS / ATILE)      // 64
#define KB      64                   // k elems staged in smem per step
#define MAXC    128                  // candidate cap per row
#define WINDOW  0.05f                // candidate window on approx scores

#define NRES (BATCH * DMODEL)        // 524288

// ---------------- persistent scratch (device globals; no allocs) -----------
__device__ __nv_bfloat16 g_dict_bf16[(size_t)ATOMS * DMODEL];     // 128 MB
__device__ float         g_resid[(size_t)BATCH * DMODEL];         // 2 MB
__device__ __nv_bfloat16 g_resid_bf16[(size_t)BATCH * DMODEL];    // 1 MB
__device__ float         g_part[(size_t)KCHUNKS * BATCH * ATOMS]; // 4 MB
__device__ float         g_lpart[512];

// ---------------- PTX helpers ----------------------------------------------
__device__ __forceinline__ uint32_t smem_u32(const void* p) {
    return (uint32_t)__cvta_generic_to_shared(p);
}
__device__ __forceinline__ void ldsm_x4(uint32_t* r, uint32_t addr) {
    asm volatile("ldmatrix.sync.aligned.m8n8.x4.shared.b16 {%0,%1,%2,%3}, [%4];\n"
        : "=r"(r[0]), "=r"(r[1]), "=r"(r[2]), "=r"(r[3]) : "r"(addr));
}
__device__ __forceinline__ void ldsm_x2(uint32_t* r, uint32_t addr) {
    asm volatile("ldmatrix.sync.aligned.m8n8.x2.shared.b16 {%0,%1}, [%2];\n"
        : "=r"(r[0]), "=r"(r[1]) : "r"(addr));
}
__device__ __forceinline__ void mma16816(float* c, const uint32_t* a, const uint32_t* b) {
    asm volatile(
        "mma.sync.aligned.m16n8k16.row.col.f32.bf16.bf16.f32 "
        "{%0,%1,%2,%3}, {%4,%5,%6,%7}, {%8,%9}, {%0,%1,%2,%3};\n"
        : "+f"(c[0]), "+f"(c[1]), "+f"(c[2]), "+f"(c[3])
        : "r"(a[0]), "r"(a[1]), "r"(a[2]), "r"(a[3]), "r"(b[0]), "r"(b[1]));
}

// ---------------- kernels ---------------------------------------------------

// dict fp32 -> bf16 (once per launch). 4 elems/thread.
__global__ void k_convert_dict(const float* __restrict__ dict) {
    size_t i = ((size_t)blockIdx.x * blockDim.x + threadIdx.x) * 4;
    float4 v = *(const float4*)(dict + i);
    __nv_bfloat16 o[4];
    o[0] = __float2bfloat16(v.x); o[1] = __float2bfloat16(v.y);
    o[2] = __float2bfloat16(v.z); o[3] = __float2bfloat16(v.w);
    *(uint2*)(g_dict_bf16 + i) = *(const uint2*)o;
}

// residual init = x (fp32 + bf16 mirror). 4 elems/thread, exact size.
__global__ void k_init(const float* __restrict__ x) {
    size_t i = ((size_t)blockIdx.x * blockDim.x + threadIdx.x) * 4;
    float4 v = *(const float4*)(x + i);
    *(float4*)(g_resid + i) = v;
    __nv_bfloat16 o[4];
    o[0] = __float2bfloat16(v.x); o[1] = __float2bfloat16(v.y);
    o[2] = __float2bfloat16(v.z); o[3] = __float2bfloat16(v.w);
    *(uint2*)(g_resid_bf16 + i) = *(const uint2*)o;
}

// Approx scores: partial[chunk][row][atom] = R_bf16 . D_bf16^T over one K-chunk.
// grid (NTILES, KCHUNKS), 256 threads (8 warps x 8 atoms each).
__global__ void __launch_bounds__(256) k_scores() {
    __shared__ __nv_bfloat16 sD[ATILE][KB + 8];  // 64 x 72 halves
    __shared__ __nv_bfloat16 sR[BATCH][KB + 8];  // 32 x 72 halves

    const int t = threadIdx.x;
    const int lane = t & 31, warp = t >> 5;
    const int atomBase = blockIdx.x * ATILE;
    const int chunk = blockIdx.y;
    const int kBase = chunk * KCHUNK;

    float c0[4] = {0.f, 0.f, 0.f, 0.f};
    float c1[4] = {0.f, 0.f, 0.f, 0.f};

    // A fragment smem addresses (constant across kb): row = lane&15, col sel by lane>=16
    const int arow = lane & 15;
    const int acolsel = (lane & 16) ? 8 : 0;
    const int brow = warp * 8 + (lane & 7);
    const int bcolsel = (lane & 8) ? 8 : 0;

    for (int kb = 0; kb < KCHUNK; kb += KB) {
        __syncthreads();
        // load dict tile: 64 rows x 64 halves = 512 x 16B; 2 per thread
        #pragma unroll
        for (int i = 0; i < 2; i++) {
            int idx = t + i * 256;
            int row = idx >> 3, seg = idx & 7;
            *(uint4*)&sD[row][seg * 8] =
                *(const uint4*)&g_dict_bf16[(size_t)(atomBase + row) * DMODEL + kBase + kb + seg * 8];
        }
        // load residual tile: 32 rows x 8 segs
        {
            int row = t >> 3, seg = t & 7;
            *(uint4*)&sR[row][seg * 8] =
                *(const uint4*)&g_resid_bf16[(size_t)row * DMODEL + kBase + kb + seg * 8];
        }
        __syncthreads();

        #pragma unroll
        for (int ks = 0; ks < 4; ks++) {
            uint32_t a0[4], a1[4], b[2];
            int col = ks * 16 + acolsel;
            ldsm_x4(a0, smem_u32(&sR[arow][col]));
            ldsm_x4(a1, smem_u32(&sR[16 + arow][col]));
            ldsm_x2(b, smem_u32(&sD[brow][ks * 16 + bcolsel]));
            mma16816(c0, a0, b);
            mma16816(c1, a1, b);
        }
    }

    // write partials: c-fragment layout -> rows/cols
    const int gr = lane >> 2;
    const int acol = atomBase + warp * 8 + (lane & 3) * 2;
    float* P = g_part + (size_t)chunk * BATCH * ATOMS;
    P[(size_t)(gr + 0)  * ATOMS + acol]     = c0[0];
    P[(size_t)(gr + 0)  * ATOMS + acol + 1] = c0[1];
    P[(size_t)(gr + 8)  * ATOMS + acol]     = c0[2];
    P[(size_t)(gr + 8)  * ATOMS + acol + 1] = c0[3];
    P[(size_t)(gr + 16) * ATOMS + acol]     = c1[0];
    P[(size_t)(gr + 16) * ATOMS + acol + 1] = c1[1];
    P[(size_t)(gr + 24) * ATOMS + acol]     = c1[2];
    P[(size_t)(gr + 24) * ATOMS + acol + 1] = c1[3];
}

// Per batch-row: reduce partials, pick candidates, exact fp32 rescore,
// softmax over candidates, sparse residual update. grid 32 x 256.
__global__ void __launch_bounds__(256) k_update(const float* __restrict__ dict) {
    __shared__ float s_scores[ATOMS];   // 16 KB
    __shared__ float s_red[256];
    __shared__ int   s_cnt;
    __shared__ int   s_idx[MAXC];
    __shared__ float s_exact[MAXC];
    __shared__ float s_w[MAXC];
    __shared__ float s_max;
    __shared__ int   s_n;

    const int r = blockIdx.x, t = threadIdx.x;
    if (t == 0) s_cnt = 0;
    __syncthreads();

    // 1. reduce K-chunk partials, track max
    float lmax = -1e30f;
    for (int a = t; a < ATOMS; a += 256) {
        float s = 0.f;
        #pragma unroll
        for (int c = 0; c < KCHUNKS; c++)
            s += g_part[((size_t)c * BATCH + r) * ATOMS + a];
        s_scores[a] = s;
        lmax = fmaxf(lmax, s);
    }
    s_red[t] = lmax; __syncthreads();
    for (int o = 128; o > 0; o >>= 1) {
        if (t < o) s_red[t] = fmaxf(s_red[t], s_red[t + o]);
        __syncthreads();
    }
    if (t == 0) s_max = s_red[0];
    __syncthreads();

    // 2. candidates within window of approx max
    const float thr = s_max - WINDOW;
    for (int a = t; a < ATOMS; a += 256) {
        if (s_scores[a] > thr) {
            int p = atomicAdd(&s_cnt, 1);
            if (p < MAXC) s_idx[p] = a;
        }
    }
    __syncthreads();
    if (t == 0) {
        int n = min(s_cnt, MAXC);
        for (int i = 1; i < n; i++) {          // sort -> deterministic order
            int v = s_idx[i], j = i - 1;
            while (j >= 0 && s_idx[j] > v) { s_idx[j + 1] = s_idx[j]; j--; }
            s_idx[j + 1] = v;
        }
        s_n = n;
    }
    __syncthreads();
    const int n = s_n;

    // 3. exact fp32 scores for candidates
    const float* R = g_resid + (size_t)r * DMODEL;
    for (int j = 0; j < n; j++) {
        const float* D = dict + (size_t)s_idx[j] * DMODEL;
        float acc = 0.f;
        for (int d = t; d < DMODEL; d += 256) acc += R[d] * D[d];
        s_red[t] = acc; __syncthreads();
        for (int o = 128; o > 0; o >>= 1) {
            if (t < o) s_red[t] += s_red[t + o];
            __syncthreads();
        }
        if (t == 0) s_exact[j] = s_red[0];
        __syncthreads();
    }

    // 4. softmax over candidates (others < e^-40, negligible)
    if (t == 0) {
        float em = -1e30f;
        for (int j = 0; j < n; j++) em = fmaxf(em, s_exact[j]);
        float den = 0.f;
        for (int j = 0; j < n; j++) {
            float w = expf((s_exact[j] - em) / TEMP);
            s_w[j] = w; den += w;
        }
        float inv = 1.f / den;
        for (int j = 0; j < n; j++) s_w[j] *= inv;
    }
    __syncthreads();

    // 5. sparse residual update + bf16 mirror
    float* Rw = g_resid + (size_t)r * DMODEL;
    for (int d = t; d < DMODEL; d += 256) {
        float v = Rw[d];
        for (int j = 0; j < n; j++)
            v -= s_w[j] * dict[(size_t)s_idx[j] * DMODEL + d];
        Rw[d] = v;
        g_resid_bf16[(size_t)r * DMODEL + d] = __float2bfloat16(v);
    }
}

// loss partials: block b sums its contiguous 1024-elem slab (deterministic tree)
__global__ void k_losspart() {
    __shared__ float s[256];
    const int b = blockIdx.x, t = threadIdx.x;
    const size_t base = (size_t)b * 1024;
    float acc = 0.f;
    for (int i = t; i < 1024; i += 256) { float v = g_resid[base + i]; acc += v * v; }
    s[t] = acc; __syncthreads();
    for (int o = 128; o > 0; o >>= 1) { if (t < o) s[t] += s[t + o]; __syncthreads(); }
    if (t == 0) g_lpart[b] = s[0];
}

__global__ void k_finalize(float* out, int out_size) {
    __shared__ float s[512];
    const int t = threadIdx.x;
    s[t] = g_lpart[t]; __syncthreads();
    for (int o = 256; o > 0; o >>= 1) { if (t < o) s[t] += s[t + o]; __syncthreads(); }
    if (t == 0 && out_size > NRES) out[0] = s[0] / (float)NRES;
}

__global__ void k_copy(float* out, int out_size) {
    const int off = (out_size > NRES) ? 1 : 0;
    size_t i = (size_t)blockIdx.x * blockDim.x + threadIdx.x;
    if (i < (size_t)NRES) out[off + i] = g_resid[i];
}

// ---------------- launch ----------------------------------------------------
extern "C" void kernel_launch(void* const* d_in, const int* in_sizes, int n_in,
                              void* d_out, int out_size) {
    const float* x = nullptr;
    const float* dict = nullptr;
    for (int i = 0; i < n_in; i++) {
        if (in_sizes[i] == NRES) x = (const float*)d_in[i];
        else if (in_sizes[i] == ATOMS * DMODEL) dict = (const float*)d_in[i];
    }
    float* out = (float*)d_out;

    k_convert_dict<<<65536, 256>>>(dict);          // 67,108,864 / 4 / 256
    k_init<<<512, 256>>>(x);                       // 524,288 / 4 / 256

    for (int it = 0; it < ITERS; it++) {
        k_scores<<<dim3(NTILES, KCHUNKS), 256>>>();
        k_update<<<BATCH, 256>>>(dict);
    }

    k_losspart<<<512, 256>>>();
    k_finalize<<<1, 512>>>(out, out_size);
    k_copy<<<2048, 256>>>(out, out_size);
}

// round 3
// speedup vs baseline: 1.8450x; 1.8450x over previous
#include <cuda_runtime.h>
#include <cuda_bf16.h>
#include <stdint.h>

#define ATOMS   4096
#define DMODEL  16384
#define BATCH   32
#define ITERS   10
#define TEMP    0.001f

#define KCHUNKS 8
#define KCHUNK  (DMODEL / KCHUNKS)   // 2048
#define ATILE   64                   // atoms per CTA
#define NTILES  (ATOMS / ATILE)      // 64
#define KB      64                   // k elems per pipeline stage
#define NSTAGE  3                    // cp.async pipeline depth
#define NSTEPS  (KCHUNK / KB)        // 32
#define MAXC    64                   // candidate cap per row
#define WINDOW  0.05f                // candidate window on approx scores

#define NRES (BATCH * DMODEL)        // 524288

// ---------------- persistent scratch (device globals; no allocs) -----------
__device__ __nv_bfloat16 g_dict_bf16[(size_t)ATOMS * DMODEL];     // 128 MB
__device__ float         g_resid[(size_t)BATCH * DMODEL];         // 2 MB
__device__ __nv_bfloat16 g_resid_bf16[(size_t)BATCH * DMODEL];    // 1 MB
__device__ float         g_part[(size_t)KCHUNKS * BATCH * ATOMS]; // 4 MB
__device__ float         g_scores[(size_t)BATCH * ATOMS];         // 512 KB
__device__ float         g_maxpart[BATCH * 8];
__device__ int           g_cand[BATCH * MAXC];
__device__ float         g_w[BATCH * MAXC];
__device__ int           g_n[BATCH];
__device__ float         g_lpart[512];

// ---------------- PTX helpers ----------------------------------------------
__device__ __forceinline__ uint32_t smem_u32(const void* p) {
    return (uint32_t)__cvta_generic_to_shared(p);
}
__device__ __forceinline__ void cpa16(uint32_t s, const void* g) {
    asm volatile("cp.async.cg.shared.global [%0], [%1], 16;\n" :: "r"(s), "l"(g));
}
__device__ __forceinline__ void cpa_commit() {
    asm volatile("cp.async.commit_group;\n");
}
__device__ __forceinline__ void cpa_wait2() {
    asm volatile("cp.async.wait_group 2;\n");
}
__device__ __forceinline__ void ldsm_x4(uint32_t* r, uint32_t addr) {
    asm volatile("ldmatrix.sync.aligned.m8n8.x4.shared.b16 {%0,%1,%2,%3}, [%4];\n"
        : "=r"(r[0]), "=r"(r[1]), "=r"(r[2]), "=r"(r[3]) : "r"(addr));
}
__device__ __forceinline__ void ldsm_x2(uint32_t* r, uint32_t addr) {
    asm volatile("ldmatrix.sync.aligned.m8n8.x2.shared.b16 {%0,%1}, [%2];\n"
        : "=r"(r[0]), "=r"(r[1]) : "r"(addr));
}
__device__ __forceinline__ void mma16816(float* c, const uint32_t* a, const uint32_t* b) {
    asm volatile(
        "mma.sync.aligned.m16n8k16.row.col.f32.bf16.bf16.f32 "
        "{%0,%1,%2,%3}, {%4,%5,%6,%7}, {%8,%9}, {%0,%1,%2,%3};\n"
        : "+f"(c[0]), "+f"(c[1]), "+f"(c[2]), "+f"(c[3])
        : "r"(a[0]), "r"(a[1]), "r"(a[2]), "r"(a[3]), "r"(b[0]), "r"(b[1]));
}

// ---------------- kernels ---------------------------------------------------

// dict fp32 -> bf16 (once per launch). 4 elems/thread.
__global__ void k_convert_dict(const float* __restrict__ dict) {
    size_t i = ((size_t)blockIdx.x * blockDim.x + threadIdx.x) * 4;
    float4 v = *(const float4*)(dict + i);
    __nv_bfloat16 o[4];
    o[0] = __float2bfloat16(v.x); o[1] = __float2bfloat16(v.y);
    o[2] = __float2bfloat16(v.z); o[3] = __float2bfloat16(v.w);
    *(uint2*)(g_dict_bf16 + i) = *(const uint2*)o;
}

// residual init = x (fp32 + bf16 mirror).
__global__ void k_init(const float* __restrict__ x) {
    size_t i = ((size_t)blockIdx.x * blockDim.x + threadIdx.x) * 4;
    float4 v = *(const float4*)(x + i);
    *(float4*)(g_resid + i) = v;
    __nv_bfloat16 o[4];
    o[0] = __float2bfloat16(v.x); o[1] = __float2bfloat16(v.y);
    o[2] = __float2bfloat16(v.z); o[3] = __float2bfloat16(v.w);
    *(uint2*)(g_resid_bf16 + i) = *(const uint2*)o;
}

// Approx scores with 3-stage cp.async pipeline.
// grid (NTILES, KCHUNKS), 256 threads.
__global__ void __launch_bounds__(256) k_scores() {
    __shared__ __nv_bfloat16 sD[NSTAGE][ATILE][KB + 8];  // 3 x 64 x 72
    __shared__ __nv_bfloat16 sR[NSTAGE][BATCH][KB + 8];  // 3 x 32 x 72

    const int t = threadIdx.x;
    const int lane = t & 31, warp = t >> 5;
    const int atomBase = blockIdx.x * ATILE;
    const int kBase = blockIdx.y * KCHUNK;

    float c0[4] = {0.f, 0.f, 0.f, 0.f};
    float c1[4] = {0.f, 0.f, 0.f, 0.f};

    const int arow = lane & 15;
    const int acolsel = (lane & 16) ? 8 : 0;
    const int brow = warp * 8 + (lane & 7);
    const int bcolsel = (lane & 8) ? 8 : 0;

    // per-thread load coordinates (fixed): dict 2 vec16, resid 1 vec16
    const int d0r = t >> 3,        d0s = t & 7;
    const int d1r = (t + 256) >> 3, d1s = t & 7;   // (t+256)&7 == t&7
    const int rr  = t >> 3,        rs = t & 7;

    auto load_stage = [&](int buf, int kb) {
        const size_t gk = (size_t)(kBase + kb);
        cpa16(smem_u32(&sD[buf][d0r][d0s * 8]),
              &g_dict_bf16[(size_t)(atomBase + d0r) * DMODEL + gk + d0s * 8]);
        cpa16(smem_u32(&sD[buf][d1r][d1s * 8]),
              &g_dict_bf16[(size_t)(atomBase + d1r) * DMODEL + gk + d1s * 8]);
        cpa16(smem_u32(&sR[buf][rr][rs * 8]),
              &g_resid_bf16[(size_t)rr * DMODEL + gk + rs * 8]);
        cpa_commit();
    };

    // prefetch NSTAGE-1 stages
    load_stage(0, 0);
    load_stage(1, KB);

    for (int s = 0; s < NSTEPS; s++) {
        if (s + NSTAGE - 1 < NSTEPS) load_stage((s + NSTAGE - 1) % NSTAGE, (s + NSTAGE - 1) * KB);
        else cpa_commit();                         // keep group count aligned
        cpa_wait2();                               // stage s resident
        __syncthreads();

        const int b = s % NSTAGE;
        #pragma unroll
        for (int ks = 0; ks < KB / 16; ks++) {
            uint32_t a0[4], a1[4], bb[2];
            int col = ks * 16 + acolsel;
            ldsm_x4(a0, smem_u32(&sR[b][arow][col]));
            ldsm_x4(a1, smem_u32(&sR[b][16 + arow][col]));
            ldsm_x2(bb, smem_u32(&sD[b][brow][ks * 16 + bcolsel]));
            mma16816(c0, a0, bb);
            mma16816(c1, a1, bb);
        }
        __syncthreads();
    }

    const int gr = lane >> 2;
    const int acol = atomBase + warp * 8 + (lane & 3) * 2;
    float* P = g_part + (size_t)blockIdx.y * BATCH * ATOMS;
    P[(size_t)(gr + 0)  * ATOMS + acol]     = c0[0];
    P[(size_t)(gr + 0)  * ATOMS + acol + 1] = c0[1];
    P[(size_t)(gr + 8)  * ATOMS + acol]     = c0[2];
    P[(size_t)(gr + 8)  * ATOMS + acol + 1] = c0[3];
    P[(size_t)(gr + 16) * ATOMS + acol]     = c1[0];
    P[(size_t)(gr + 16) * ATOMS + acol + 1] = c1[1];
    P[(size_t)(gr + 24) * ATOMS + acol]     = c1[2];
    P[(size_t)(gr + 24) * ATOMS + acol + 1] = c1[3];
}

// Reduce K-chunk partials -> full scores + per-block max. grid (8, 32) x 256.
__global__ void __launch_bounds__(256) k_reduce() {
    __shared__ float sm[256];
    const int ab = blockIdx.x, r = blockIdx.y, t = threadIdx.x;
    float lmax = -1e30f;
    #pragma unroll
    for (int i = 0; i < 2; i++) {
        int a = ab * 512 + i * 256 + t;
        float s = 0.f;
        #pragma unroll
        for (int c = 0; c < KCHUNKS; c++)
            s += g_part[((size_t)c * BATCH + r) * ATOMS + a];
        g_scores[(size_t)r * ATOMS + a] = s;
        lmax = fmaxf(lmax, s);
    }
    sm[t] = lmax; __syncthreads();
    for (int o = 128; o > 0; o >>= 1) {
        if (t < o) sm[t] = fmaxf(sm[t], sm[t + o]);
        __syncthreads();
    }
    if (t == 0) g_maxpart[r * 8 + ab] = sm[0];
}

// Per row: max, candidate select, exact fp32 rescore, softmax. grid 32 x 1024.
__global__ void __launch_bounds__(1024) k_select(const float* __restrict__ dict) {
    __shared__ float sred[32];
    __shared__ float s_thr;
    __shared__ int   s_cnt, s_n;
    __shared__ int   s_idx[MAXC];
    __shared__ float s_ex[MAXC];

    const int r = blockIdx.x, t = threadIdx.x;
    const int lane = t & 31, w = t >> 5;

    if (t == 0) {
        s_cnt = 0;
        float mm = -1e30f;
        #pragma unroll
        for (int i = 0; i < 8; i++) mm = fmaxf(mm, g_maxpart[r * 8 + i]);
        s_thr = mm - WINDOW;
    }
    __syncthreads();
    const float thr = s_thr;

    #pragma unroll
    for (int i = 0; i < 4; i++) {
        int a = i * 1024 + t;
        if (g_scores[(size_t)r * ATOMS + a] > thr) {
            int p = atomicAdd(&s_cnt, 1);
            if (p < MAXC) s_idx[p] = a;
        }
    }
    __syncthreads();
    if (t == 0) {
        int n = min(s_cnt, MAXC);
        for (int i = 1; i < n; i++) {
            int v = s_idx[i], j = i - 1;
            while (j >= 0 && s_idx[j] > v) { s_idx[j + 1] = s_idx[j]; j--; }
            s_idx[j + 1] = v;
        }
        s_n = n;
    }
    __syncthreads();
    const int n = s_n;

    const float* R = g_resid + (size_t)r * DMODEL;
    for (int j = 0; j < n; j++) {
        const float* D = dict + (size_t)s_idx[j] * DMODEL;
        float acc = 0.f;
        #pragma unroll 4
        for (int d = t; d < DMODEL; d += 1024) acc += R[d] * D[d];
        #pragma unroll
        for (int o = 16; o > 0; o >>= 1) acc += __shfl_xor_sync(0xffffffffu, acc, o);
        if (lane == 0) sred[w] = acc;
        __syncthreads();
        if (t == 0) {
            float s = 0.f;
            #pragma unroll
            for (int i = 0; i < 32; i++) s += sred[i];
            s_ex[j] = s;
        }
        __syncthreads();
    }

    if (t == 0) {
        float em = -1e30f;
        for (int j = 0; j < n; j++) em = fmaxf(em, s_ex[j]);
        float den = 0.f;
        float wv[MAXC];
        for (int j = 0; j < n; j++) { wv[j] = expf((s_ex[j] - em) / TEMP); den += wv[j]; }
        float inv = 1.f / den;
        for (int j = 0; j < n; j++) {
            g_w[r * MAXC + j] = wv[j] * inv;
            g_cand[r * MAXC + j] = s_idx[j];
        }
        g_n[r] = n;
    }
}

// Sparse residual update + bf16 mirror. grid (16, 32) x 256, float4 per thread.
__global__ void __launch_bounds__(256) k_apply(const float* __restrict__ dict) {
    const int cb = blockIdx.x, r = blockIdx.y, t = threadIdx.x;
    const int n = g_n[r];
    const int col = cb * 1024 + t * 4;
    const size_t base = (size_t)r * DMODEL + col;

    float4 v = *(const float4*)(g_resid + base);
    for (int j = 0; j < n; j++) {
        const float wj = g_w[r * MAXC + j];
        const float4 dv = *(const float4*)(dict + (size_t)g_cand[r * MAXC + j] * DMODEL + col);
        v.x -= wj * dv.x; v.y -= wj * dv.y; v.z -= wj * dv.z; v.w -= wj * dv.w;
    }
    *(float4*)(g_resid + base) = v;
    __nv_bfloat16 o[4];
    o[0] = __float2bfloat16(v.x); o[1] = __float2bfloat16(v.y);
    o[2] = __float2bfloat16(v.z); o[3] = __float2bfloat16(v.w);
    *(uint2*)(g_resid_bf16 + base) = *(const uint2*)o;
}

// loss partials: block b sums its contiguous 1024-elem slab
__global__ void k_losspart() {
    __shared__ float s[256];
    const int b = blockIdx.x, t = threadIdx.x;
    const size_t base = (size_t)b * 1024;
    float acc = 0.f;
    for (int i = t; i < 1024; i += 256) { float v = g_resid[base + i]; acc += v * v; }
    s[t] = acc; __syncthreads();
    for (int o = 128; o > 0; o >>= 1) { if (t < o) s[t] += s[t + o]; __syncthreads(); }
    if (t == 0) g_lpart[b] = s[0];
}

__global__ void k_finalize(float* out, int out_size) {
    __shared__ float s[512];
    const int t = threadIdx.x;
    s[t] = g_lpart[t]; __syncthreads();
    for (int o = 256; o > 0; o >>= 1) { if (t < o) s[t] += s[t + o]; __syncthreads(); }
    if (t == 0 && out_size > NRES) out[0] = s[0] / (float)NRES;
}

__global__ void k_copy(float* out, int out_size) {
    const int off = (out_size > NRES) ? 1 : 0;
    size_t i = (size_t)blockIdx.x * blockDim.x + threadIdx.x;
    if (i < (size_t)NRES) out[off + i] = g_resid[i];
}

// ---------------- launch ----------------------------------------------------
extern "C" void kernel_launch(void* const* d_in, const int* in_sizes, int n_in,
                              void* d_out, int out_size) {
    const float* x = nullptr;
    const float* dict = nullptr;
    for (int i = 0; i < n_in; i++) {
        if (in_sizes[i] == NRES) x = (const float*)d_in[i];
        else if (in_sizes[i] == ATOMS * DMODEL) dict = (const float*)d_in[i];
    }
    float* out = (float*)d_out;

    k_convert_dict<<<65536, 256>>>(dict);
    k_init<<<512, 256>>>(x);

    for (int it = 0; it < ITERS; it++) {
        k_scores<<<dim3(NTILES, KCHUNKS), 256>>>();
        k_reduce<<<dim3(8, BATCH), 256>>>();
        k_select<<<BATCH, 1024>>>(dict);
        k_apply<<<dim3(16, BATCH), 256>>>(dict);
    }

    k_losspart<<<512, 256>>>();
    k_finalize<<<1, 512>>>(out, out_size);
    k_copy<<<2048, 256>>>(out, out_size);
}